// round 15
// baseline (speedup 1.0000x reference)
#include <cuda_runtime.h>
#include <cuda_fp16.h>
#include <cstdint>

#define NROWS 8192
#define DIN   256
#define DOUT  128
#define KC    64
#define TILE_M 128
#define NCTA  296
#define SLOTS 6

// ---- device-global scratch (no allocations allowed; zero-initialized) ----
__device__ __half g_h[(size_t)NROWS * DOUT];   // h fp16 row-major
__device__ __half g_Wh[(size_t)DIN * DOUT];
__device__ __half g_Wl[(size_t)DIN * DOUT];
__device__ float  g_B[NROWS];
__device__ float  g_D[NROWS];
__device__ float  g_E[NROWS];
__device__ float  g_acc[SLOTS][(size_t)NROWS * DOUT];  // slot partials (zero-init)
__device__ float  g_rs[SLOTS][NROWS];                  // rowsum partials (zero-init)
__device__ unsigned int g_cnt[NROWS / TILE_M];         // tile arrival counters (zero-init)

__device__ __forceinline__ uint32_t smem_u32(const void* p) {
    uint32_t a;
    asm("{ .reg .u64 t; cvta.to.shared.u64 t, %1; cvt.u32.u64 %0, t; }" : "=r"(a) : "l"(p));
    return a;
}

// streaming (evict-first) 16B global loads — for one-pass data
__device__ __forceinline__ int4 ldg_cs(const int4* p) {
    int4 v;
    asm("ld.global.cs.v4.u32 {%0,%1,%2,%3}, [%4];"
        : "=r"(v.x), "=r"(v.y), "=r"(v.z), "=r"(v.w) : "l"(p));
    return v;
}
__device__ __forceinline__ float4 ldg_cs_f4(const float4* p) {
    float4 v;
    asm("ld.global.cs.v4.f32 {%0,%1,%2,%3}, [%4];"
        : "=f"(v.x), "=f"(v.y), "=f"(v.z), "=f"(v.w) : "l"(p));
    return v;
}

#define CP_ASYNC16(dst, src) \
    asm volatile("cp.async.cg.shared.global [%0], [%1], 16;" :: "r"(dst), "l"(src) : "memory")
#define CP_COMMIT() asm volatile("cp.async.commit_group;" ::: "memory")
#define CP_WAIT0()  asm volatile("cp.async.wait_group 0;" ::: "memory")

// ============ K0: split W into fp16 hi/lo ============
__global__ __launch_bounds__(256) void k0_splitW(const float* __restrict__ W)
{
    size_t e = ((size_t)blockIdx.x * 256 + threadIdx.x) * 8;
    float4 v0 = __ldg((const float4*)(W + e));
    float4 v1 = __ldg((const float4*)(W + e + 4));
    __half hi[8], lo[8];
    const float* v = (const float*)&v0;
    #pragma unroll
    for (int i = 0; i < 4; i++) {
        hi[i] = __float2half_rn(v[i]);
        lo[i] = __float2half_rn(v[i] - __half2float(hi[i]));
    }
    v = (const float*)&v1;
    #pragma unroll
    for (int i = 0; i < 4; i++) {
        hi[4 + i] = __float2half_rn(v[i]);
        lo[4 + i] = __float2half_rn(v[i] - __half2float(hi[4 + i]));
    }
    *(uint4*)(g_Wh + e) = *(const uint4*)hi;
    *(uint4*)(g_Wl + e) = *(const uint4*)lo;
}

// ============ K1: h = xW + b via split-fp16 HMMA (x split fused), plus B/D/E ============
#define K1ASTR 72u
#define K1BSTR 136u
#define K1XSTR 68u
#define K1_XS  0u
#define K1_AH  8704u
#define K1_AL  13312u
#define K1_BH  17920u
#define K1_BL  35328u
#define K1BUF  52736u
#define SMEM_K1 (2 * 52736)

__global__ __launch_bounds__(256, 2) void k1_mma(
    const float* __restrict__ x,
    const float* __restrict__ bW, const float* __restrict__ a1,
    const float* __restrict__ a2, const float* __restrict__ ba_p)
{
    extern __shared__ char smem[];
    const uint32_t sb = smem_u32(smem);
    __shared__ float red1[32][4];
    __shared__ float red2[32][4];

    const int tid  = threadIdx.x;
    const int wid  = tid >> 5;
    const int lane = tid & 31;
    const int rb   = blockIdx.x * 32;
    const int mwarp = wid & 1;
    const int nwarp = wid >> 1;

    const int g  = lane >> 3;
    const int l7 = lane & 7;
    const uint32_t aOff = (uint32_t)(mwarp * 16 + (g & 1) * 8 + l7) * K1ASTR + (uint32_t)((g >> 1) * 8);
    const uint32_t bOff = (uint32_t)((g & 1) * 8 + l7) * K1BSTR + (uint32_t)((g >> 1) * 8) + (uint32_t)nwarp * 32u;

    const int crow = tid >> 3;
    const int cc8  = (tid & 7) * 8;

    float facc[4][4];
    #pragma unroll
    for (int n = 0; n < 4; n++)
        #pragma unroll
        for (int c = 0; c < 4; c++) facc[n][c] = 0.f;

    auto stage = [&](int buf, int chunk) {
        const uint32_t base = sb + (uint32_t)buf * K1BUF;
        const int kc = chunk * 64;
        #pragma unroll
        for (int i = 0; i < 2; i++) {
            int pe = tid + 256 * i;
            int r = pe >> 4, p = pe & 15;
            CP_ASYNC16(base + K1_XS + (uint32_t)r * (K1XSTR * 4u) + (uint32_t)p * 16u,
                       x + (size_t)(rb + r) * DIN + kc + p * 4);
        }
        #pragma unroll
        for (int i = 0; i < 4; i++) {
            int e2 = tid + 256 * i;
            int k = e2 >> 4, p = e2 & 15;
            uint32_t d = (uint32_t)k * (K1BSTR * 2u) + (uint32_t)p * 16u;
            CP_ASYNC16(base + K1_BH + d, g_Wh + (size_t)(kc + k) * DOUT + p * 8);
            CP_ASYNC16(base + K1_BL + d, g_Wl + (size_t)(kc + k) * DOUT + p * 8);
        }
        CP_COMMIT();
    };

    stage(0, 0);
    for (int cc = 0; cc < 4; ++cc) {
        const int buf = cc & 1;
        const uint32_t base = sb + (uint32_t)buf * K1BUF;
        CP_WAIT0();
        __syncthreads();

        {
            float v[8];
            uint32_t xaddr = base + K1_XS + (uint32_t)crow * (K1XSTR * 4u) + (uint32_t)cc8 * 4u;
            asm("ld.shared.v4.f32 {%0,%1,%2,%3}, [%4];"
                : "=f"(v[0]), "=f"(v[1]), "=f"(v[2]), "=f"(v[3]) : "r"(xaddr));
            asm("ld.shared.v4.f32 {%0,%1,%2,%3}, [%4];"
                : "=f"(v[4]), "=f"(v[5]), "=f"(v[6]), "=f"(v[7]) : "r"(xaddr + 16u));
            __half hi[8], lo[8];
            #pragma unroll
            for (int i = 0; i < 8; i++) {
                hi[i] = __float2half_rn(v[i]);
                lo[i] = __float2half_rn(v[i] - __half2float(hi[i]));
            }
            uint32_t hdst = base + K1_AH + ((uint32_t)crow * K1ASTR + (uint32_t)cc8) * 2u;
            uint32_t ldst = base + K1_AL + ((uint32_t)crow * K1ASTR + (uint32_t)cc8) * 2u;
            const uint32_t* hw = (const uint32_t*)hi;
            const uint32_t* lw = (const uint32_t*)lo;
            asm volatile("st.shared.v4.b32 [%0], {%1,%2,%3,%4};"
                :: "r"(hdst), "r"(hw[0]), "r"(hw[1]), "r"(hw[2]), "r"(hw[3]) : "memory");
            asm volatile("st.shared.v4.b32 [%0], {%1,%2,%3,%4};"
                :: "r"(ldst), "r"(lw[0]), "r"(lw[1]), "r"(lw[2]), "r"(lw[3]) : "memory");
        }
        __syncthreads();

        if (cc < 3) stage(buf ^ 1, cc + 1);

        #pragma unroll
        for (int ss = 0; ss < 4; ++ss) {
            uint32_t Ah[4], Al[4];
            asm volatile("ldmatrix.sync.aligned.m8n8.x4.shared.b16 {%0,%1,%2,%3}, [%4];"
                : "=r"(Ah[0]), "=r"(Ah[1]), "=r"(Ah[2]), "=r"(Ah[3])
                : "r"(base + K1_AH + (aOff + (uint32_t)ss * 16u) * 2u));
            asm volatile("ldmatrix.sync.aligned.m8n8.x4.shared.b16 {%0,%1,%2,%3}, [%4];"
                : "=r"(Al[0]), "=r"(Al[1]), "=r"(Al[2]), "=r"(Al[3])
                : "r"(base + K1_AL + (aOff + (uint32_t)ss * 16u) * 2u));
            #pragma unroll
            for (int ntg = 0; ntg < 2; ++ntg) {
                uint32_t bh0, bh1, bh2, bh3, bl0, bl1, bl2, bl3;
                uint32_t baddr = (bOff + (uint32_t)ss * 16u * K1BSTR + (uint32_t)ntg * 16u) * 2u;
                asm volatile("ldmatrix.sync.aligned.m8n8.x4.trans.shared.b16 {%0,%1,%2,%3}, [%4];"
                    : "=r"(bh0), "=r"(bh1), "=r"(bh2), "=r"(bh3) : "r"(base + K1_BH + baddr));
                asm volatile("ldmatrix.sync.aligned.m8n8.x4.trans.shared.b16 {%0,%1,%2,%3}, [%4];"
                    : "=r"(bl0), "=r"(bl1), "=r"(bl2), "=r"(bl3) : "r"(base + K1_BL + baddr));
                float* d0 = facc[ntg * 2];
                float* d1 = facc[ntg * 2 + 1];
                asm volatile("mma.sync.aligned.m16n8k16.row.col.f32.f16.f16.f32 "
                    "{%0,%1,%2,%3}, {%4,%5,%6,%7}, {%8,%9}, {%0,%1,%2,%3};"
                    : "+f"(d0[0]), "+f"(d0[1]), "+f"(d0[2]), "+f"(d0[3])
                    : "r"(Ah[0]), "r"(Ah[1]), "r"(Ah[2]), "r"(Ah[3]), "r"(bh0), "r"(bh1));
                asm volatile("mma.sync.aligned.m16n8k16.row.col.f32.f16.f16.f32 "
                    "{%0,%1,%2,%3}, {%4,%5,%6,%7}, {%8,%9}, {%0,%1,%2,%3};"
                    : "+f"(d1[0]), "+f"(d1[1]), "+f"(d1[2]), "+f"(d1[3])
                    : "r"(Ah[0]), "r"(Ah[1]), "r"(Ah[2]), "r"(Ah[3]), "r"(bh2), "r"(bh3));
                asm volatile("mma.sync.aligned.m16n8k16.row.col.f32.f16.f16.f32 "
                    "{%0,%1,%2,%3}, {%4,%5,%6,%7}, {%8,%9}, {%0,%1,%2,%3};"
                    : "+f"(d0[0]), "+f"(d0[1]), "+f"(d0[2]), "+f"(d0[3])
                    : "r"(Ah[0]), "r"(Ah[1]), "r"(Ah[2]), "r"(Ah[3]), "r"(bl0), "r"(bl1));
                asm volatile("mma.sync.aligned.m16n8k16.row.col.f32.f16.f16.f32 "
                    "{%0,%1,%2,%3}, {%4,%5,%6,%7}, {%8,%9}, {%0,%1,%2,%3};"
                    : "+f"(d1[0]), "+f"(d1[1]), "+f"(d1[2]), "+f"(d1[3])
                    : "r"(Ah[0]), "r"(Ah[1]), "r"(Ah[2]), "r"(Ah[3]), "r"(bl2), "r"(bl3));
                asm volatile("mma.sync.aligned.m16n8k16.row.col.f32.f16.f16.f32 "
                    "{%0,%1,%2,%3}, {%4,%5,%6,%7}, {%8,%9}, {%0,%1,%2,%3};"
                    : "+f"(d0[0]), "+f"(d0[1]), "+f"(d0[2]), "+f"(d0[3])
                    : "r"(Al[0]), "r"(Al[1]), "r"(Al[2]), "r"(Al[3]), "r"(bh0), "r"(bh1));
                asm volatile("mma.sync.aligned.m16n8k16.row.col.f32.f16.f16.f32 "
                    "{%0,%1,%2,%3}, {%4,%5,%6,%7}, {%8,%9}, {%0,%1,%2,%3};"
                    : "+f"(d1[0]), "+f"(d1[1]), "+f"(d1[2]), "+f"(d1[3])
                    : "r"(Al[0]), "r"(Al[1]), "r"(Al[2]), "r"(Al[3]), "r"(bh2), "r"(bh3));
            }
        }
        __syncthreads();
    }

    // ---- epilogue: bias, h write, s1/s2, E/B/D ----
    const int r  = lane >> 2;
    const int c2 = (lane & 3) * 2;
    const int row0 = mwarp * 16 + r;
    float s1a = 0.f, s2a = 0.f, s1b = 0.f, s2b = 0.f;

    #pragma unroll
    for (int nt = 0; nt < 4; ++nt) {
        const int col = nwarp * 32 + nt * 8 + c2;
        float2 bv = *(const float2*)&bW[col];
        float2 a1v = *(const float2*)&a1[col];
        float2 a2v = *(const float2*)&a2[col];
        float h00 = facc[nt][0] + bv.x, h01 = facc[nt][1] + bv.y;
        float h10 = facc[nt][2] + bv.x, h11 = facc[nt][3] + bv.y;
        __half2 p0 = __floats2half2_rn(h00, h01);
        __half2 p1 = __floats2half2_rn(h10, h11);
        *(uint32_t*)(g_h + (size_t)(rb + row0) * DOUT + col)     = *(const uint32_t*)&p0;
        *(uint32_t*)(g_h + (size_t)(rb + row0 + 8) * DOUT + col) = *(const uint32_t*)&p1;
        s1a += h00 * a1v.x + h01 * a1v.y;
        s2a += h00 * a2v.x + h01 * a2v.y;
        s1b += h10 * a1v.x + h11 * a1v.y;
        s2b += h10 * a2v.x + h11 * a2v.y;
    }
    #pragma unroll
    for (int m = 1; m <= 2; m <<= 1) {
        s1a += __shfl_xor_sync(0xffffffffu, s1a, m);
        s2a += __shfl_xor_sync(0xffffffffu, s2a, m);
        s1b += __shfl_xor_sync(0xffffffffu, s1b, m);
        s2b += __shfl_xor_sync(0xffffffffu, s2b, m);
    }
    if ((lane & 3) == 0) {
        red1[row0][nwarp] = s1a;  red2[row0][nwarp] = s2a;
        red1[row0 + 8][nwarp] = s1b;  red2[row0 + 8][nwarp] = s2b;
    }
    __syncthreads();
    if (tid < 32) {
        float s1 = red1[tid][0] + red1[tid][1] + red1[tid][2] + red1[tid][3];
        float s2 = red2[tid][0] + red2[tid][1] + red2[tid][2] + red2[tid][3];
        float u = s1 + ba_p[0];
        g_E[rb + tid] = expf(-0.99f * u);
        g_B[rb + tid] = expf(s2);
        g_D[rb + tid] = expf(0.01f * s2);
    }
}

// ============ K2: fused GEMM + last-CTA tile reduction (writes out directly) ============
#define PSTR 72u
#define HSTR 136u
#define PBUF (128u * PSTR * 2u)
#define HBUF (64u * HSTR * 2u)
#define SMEM_K2 (2 * 18432 + 2 * 17408)

__global__ __launch_bounds__(256, 2) void k2_fused(const int* __restrict__ adj,
                                                   float* __restrict__ out)
{
    extern __shared__ char smem[];
    const uint32_t sPb = smem_u32(smem);
    const uint32_t sHb = sPb + 2u * PBUF;
    __shared__ int   s_isLast;
    __shared__ float s_inv[TILE_M];

    const int tid  = threadIdx.x;
    const int wid  = tid >> 5;
    const int lane = tid & 31;
    const int cta  = blockIdx.x;
    const int slot = cta % SLOTS;

    const int s = (1024 * cta) / 37;
    const int e = (1024 * (cta + 1)) / 37;

    const int tr  = tid >> 3;
    const int jq8 = tid & 7;
    const int hjr = tid >> 2;
    const int hcb = (tid & 3) * 64;

    const int mwarp = wid & 3;
    const int nwarp = wid >> 2;
    const uint32_t ncol0 = (uint32_t)nwarp * 64u;

    const int g  = lane >> 3;
    const int l7 = lane & 7;
    const uint32_t aRow0 = (uint32_t)(mwarp * 32 + (g & 1) * 8 + l7) * PSTR + (uint32_t)((g >> 1) * 8);
    const uint32_t aRow1 = aRow0 + 16u * PSTR;
    const uint32_t bBase = (uint32_t)((g & 1) * 8 + l7) * HSTR + (uint32_t)((g >> 1) * 8) + ncol0;

    const uint32_t sPst = ((uint32_t)tr * PSTR + (uint32_t)jq8 * 8u) * 2u;
    const uint32_t sHst = (uint32_t)hjr * HSTR * 2u + (uint32_t)hcb;

    const float* Bp = g_B + jq8 * 8;
    const float* Dp = g_D + jq8 * 8;

    const int t0 = s >> 7, t1 = (e - 1) >> 7;
    for (int t = t0; t <= t1; ++t) {
        const int c0 = (s > (t << 7)) ? s : (t << 7);
        const int c1 = (e < ((t + 1) << 7)) ? e : ((t + 1) << 7);
        const int rowb = t * TILE_M;

        float Ei[4];
        #pragma unroll
        for (int k = 0; k < 4; k++) Ei[k] = g_E[rowb + tr + 32 * k];

        const int* adjbase = adj + (size_t)(rowb + tr) * NROWS + jq8 * 8;

        float facc[16][4];
        #pragma unroll
        for (int n = 0; n < 16; n++)
            #pragma unroll
            for (int c = 0; c < 4; c++) facc[n][c] = 0.f;
        float rsum[4] = {0.f, 0.f, 0.f, 0.f};

        int4 adjr[8];
        float4 B0r, B1r, D0r, D1r;

        auto produce_k = [&](int k, uint32_t stb) {
            int4 a0 = adjr[2 * k], a1 = adjr[2 * k + 1];
            float v0 = fmaxf(B0r.x, Ei[k] * D0r.x); v0 = a0.x ? v0 : 0.f;
            float v1 = fmaxf(B0r.y, Ei[k] * D0r.y); v1 = a0.y ? v1 : 0.f;
            float v2 = fmaxf(B0r.z, Ei[k] * D0r.z); v2 = a0.z ? v2 : 0.f;
            float v3 = fmaxf(B0r.w, Ei[k] * D0r.w); v3 = a0.w ? v3 : 0.f;
            float v4 = fmaxf(B1r.x, Ei[k] * D1r.x); v4 = a1.x ? v4 : 0.f;
            float v5 = fmaxf(B1r.y, Ei[k] * D1r.y); v5 = a1.y ? v5 : 0.f;
            float v6 = fmaxf(B1r.z, Ei[k] * D1r.z); v6 = a1.z ? v6 : 0.f;
            float v7 = fmaxf(B1r.w, Ei[k] * D1r.w); v7 = a1.w ? v7 : 0.f;
            rsum[k] += ((v0 + v1) + (v2 + v3)) + ((v4 + v5) + (v6 + v7));
            __half2 p0 = __floats2half2_rn(v0, v1);
            __half2 p1 = __floats2half2_rn(v2, v3);
            __half2 p2 = __floats2half2_rn(v4, v5);
            __half2 p3 = __floats2half2_rn(v6, v7);
            asm volatile("st.shared.v4.b32 [%0], {%1,%2,%3,%4};"
                :: "r"(stb + (uint32_t)(32 * k) * PSTR * 2u),
                   "r"(*(const uint32_t*)&p0), "r"(*(const uint32_t*)&p1),
                   "r"(*(const uint32_t*)&p2), "r"(*(const uint32_t*)&p3) : "memory");
        };

        {
            const int jb = (c0 & 127) * KC;
            #pragma unroll
            for (int k = 0; k < 4; k++) {
                const int4* p = (const int4*)(adjbase + (size_t)(32 * k) * NROWS + jb);
                adjr[2 * k]     = ldg_cs(p);
                adjr[2 * k + 1] = ldg_cs(p + 1);
            }
            const char* hsrc = (const char*)g_h + ((size_t)(jb + hjr) * DOUT) * 2 + hcb;
            #pragma unroll
            for (int q = 0; q < 4; q++)
                CP_ASYNC16(sHb + sHst + (uint32_t)q * 16u, hsrc + q * 16);
            CP_COMMIT();
            B0r = __ldg((const float4*)(Bp + jb));
            B1r = __ldg((const float4*)(Bp + jb + 4));
            D0r = __ldg((const float4*)(Dp + jb));
            D1r = __ldg((const float4*)(Dp + jb + 4));
            CP_WAIT0();
            #pragma unroll
            for (int k = 0; k < 4; k++) produce_k(k, sPb + sPst);
        }
        __syncthreads();

        for (int cc = c0; cc < c1; ++cc) {
            const int b = (cc - c0) & 1;
            const uint32_t Pcur = sPb + (uint32_t)b * PBUF;
            const uint32_t Hcur = sHb + (uint32_t)b * HBUF;
            const uint32_t Pnxt = sPb + (uint32_t)(b ^ 1) * PBUF;
            const uint32_t Hnxt = sHb + (uint32_t)(b ^ 1) * HBUF;
            const bool more = (cc + 1 < c1);
            const int jbn = ((cc + 1) & 127) * KC;

            if (more) {
                #pragma unroll
                for (int k = 0; k < 4; k++) {
                    const int4* p = (const int4*)(adjbase + (size_t)(32 * k) * NROWS + jbn);
                    adjr[2 * k]     = ldg_cs(p);
                    adjr[2 * k + 1] = ldg_cs(p + 1);
                }
                const char* hsrc = (const char*)g_h + ((size_t)(jbn + hjr) * DOUT) * 2 + hcb;
                #pragma unroll
                for (int q = 0; q < 4; q++)
                    CP_ASYNC16(Hnxt + sHst + (uint32_t)q * 16u, hsrc + q * 16);
                CP_COMMIT();
                B0r = __ldg((const float4*)(Bp + jbn));
                B1r = __ldg((const float4*)(Bp + jbn + 4));
                D0r = __ldg((const float4*)(Dp + jbn));
                D1r = __ldg((const float4*)(Dp + jbn + 4));
            }

            #pragma unroll
            for (int ss = 0; ss < 4; ++ss) {
                uint32_t A0[4], A1[4];
                asm volatile("ldmatrix.sync.aligned.m8n8.x4.shared.b16 {%0,%1,%2,%3}, [%4];"
                    : "=r"(A0[0]), "=r"(A0[1]), "=r"(A0[2]), "=r"(A0[3])
                    : "r"(Pcur + (aRow0 + (uint32_t)ss * 16u) * 2u));
                asm volatile("ldmatrix.sync.aligned.m8n8.x4.shared.b16 {%0,%1,%2,%3}, [%4];"
                    : "=r"(A1[0]), "=r"(A1[1]), "=r"(A1[2]), "=r"(A1[3])
                    : "r"(Pcur + (aRow1 + (uint32_t)ss * 16u) * 2u));
                #pragma unroll
                for (int nt = 0; nt < 4; ++nt) {
                    uint32_t b0, b1, b2, b3;
                    asm volatile("ldmatrix.sync.aligned.m8n8.x4.trans.shared.b16 {%0,%1,%2,%3}, [%4];"
                        : "=r"(b0), "=r"(b1), "=r"(b2), "=r"(b3)
                        : "r"(Hcur + (bBase + (uint32_t)ss * 16u * HSTR + (uint32_t)nt * 16u) * 2u));
                    float* d00 = facc[nt * 2];
                    float* d01 = facc[nt * 2 + 1];
                    float* d10 = facc[8 + nt * 2];
                    float* d11 = facc[8 + nt * 2 + 1];
                    asm volatile("mma.sync.aligned.m16n8k16.row.col.f32.f16.f16.f32 "
                        "{%0,%1,%2,%3}, {%4,%5,%6,%7}, {%8,%9}, {%0,%1,%2,%3};"
                        : "+f"(d00[0]), "+f"(d00[1]), "+f"(d00[2]), "+f"(d00[3])
                        : "r"(A0[0]), "r"(A0[1]), "r"(A0[2]), "r"(A0[3]), "r"(b0), "r"(b1));
                    asm volatile("mma.sync.aligned.m16n8k16.row.col.f32.f16.f16.f32 "
                        "{%0,%1,%2,%3}, {%4,%5,%6,%7}, {%8,%9}, {%0,%1,%2,%3};"
                        : "+f"(d01[0]), "+f"(d01[1]), "+f"(d01[2]), "+f"(d01[3])
                        : "r"(A0[0]), "r"(A0[1]), "r"(A0[2]), "r"(A0[3]), "r"(b2), "r"(b3));
                    asm volatile("mma.sync.aligned.m16n8k16.row.col.f32.f16.f16.f32 "
                        "{%0,%1,%2,%3}, {%4,%5,%6,%7}, {%8,%9}, {%0,%1,%2,%3};"
                        : "+f"(d10[0]), "+f"(d10[1]), "+f"(d10[2]), "+f"(d10[3])
                        : "r"(A1[0]), "r"(A1[1]), "r"(A1[2]), "r"(A1[3]), "r"(b0), "r"(b1));
                    asm volatile("mma.sync.aligned.m16n8k16.row.col.f32.f16.f16.f32 "
                        "{%0,%1,%2,%3}, {%4,%5,%6,%7}, {%8,%9}, {%0,%1,%2,%3};"
                        : "+f"(d11[0]), "+f"(d11[1]), "+f"(d11[2]), "+f"(d11[3])
                        : "r"(A1[0]), "r"(A1[1]), "r"(A1[2]), "r"(A1[3]), "r"(b2), "r"(b3));
                }
                if (more) produce_k(ss, Pnxt + sPst);
            }

            CP_WAIT0();
            __syncthreads();
        }

        // ---- flush partials for this tile into slot buffers ----
        {
            const int r  = lane >> 2;
            const int c2 = (lane & 3) * 2;
            #pragma unroll
            for (int mt = 0; mt < 2; ++mt) {
                const int row0 = rowb + mwarp * 32 + mt * 16 + r;
                float* dst0 = &g_acc[slot][(size_t)row0 * DOUT];
                float* dst1 = dst0 + (size_t)8 * DOUT;
                #pragma unroll
                for (int nt = 0; nt < 4; ++nt) {
                    #pragma unroll
                    for (int hh = 0; hh < 2; ++hh) {
                        const float* f = facc[mt * 8 + nt * 2 + hh];
                        int col = nwarp * 64 + nt * 16 + hh * 8 + c2;
                        *(float2*)(dst0 + col) = make_float2(f[0], f[1]);
                        *(float2*)(dst1 + col) = make_float2(f[2], f[3]);
                    }
                }
            }
        }
        #pragma unroll
        for (int m = 1; m <= 4; m <<= 1) {
            #pragma unroll
            for (int k = 0; k < 4; k++)
                rsum[k] += __shfl_xor_sync(0xffffffffu, rsum[k], m);
        }
        if (jq8 == 0) {
            #pragma unroll
            for (int k = 0; k < 4; k++)
                g_rs[slot][rowb + tr + 32 * k] = rsum[k];
        }

        // ---- last-contributor tile reduction -> final output ----
        __threadfence();
        if (tid == 0) {
            int cfirst = (37 * (t << 7) + 36) >> 10;
            int clast  = (37 * (((t + 1) << 7) - 1) + 36) >> 10;
            unsigned int expct = (unsigned int)(clast - cfirst + 1);
            unsigned int prev = atomicAdd(&g_cnt[t], 1u);
            s_isLast = (prev == expct - 1u) ? 1 : 0;
        }
        __syncthreads();
        if (s_isLast) {
            if (tid < TILE_M) {
                float rs = 0.f;
                #pragma unroll
                for (int s2 = 0; s2 < SLOTS; s2++) rs += g_rs[s2][rowb + tid];
                s_inv[tid] = 1.0f / rs;
            }
            __syncthreads();
            const float4* accb[SLOTS];
            #pragma unroll
            for (int s2 = 0; s2 < SLOTS; s2++)
                accb[s2] = (const float4*)&g_acc[s2][(size_t)rowb * DOUT];
            float4* outb = (float4*)(out + (size_t)rowb * DOUT);
            #pragma unroll
            for (int i = 0; i < 16; ++i) {
                int p = tid + 256 * i;           // 0..4095 float4 positions in tile
                float4 o = make_float4(0.f, 0.f, 0.f, 0.f);
                #pragma unroll
                for (int s2 = 0; s2 < SLOTS; s2++) {
                    float4 a = ldg_cs_f4(accb[s2] + p);
                    o.x += a.x; o.y += a.y; o.z += a.z; o.w += a.w;
                }
                float inv = s_inv[p >> 5];
                o.x *= inv; o.y *= inv; o.z *= inv; o.w *= inv;
                outb[p] = o;
            }
            if (tid == 0) g_cnt[t] = 0;          // reset for next graph replay
        }
        __syncthreads();   // smem reuse safety across segments
    }
}

extern "C" void kernel_launch(void* const* d_in, const int* in_sizes, int n_in,
                              void* d_out, int out_size) {
    const float* x   = (const float*)d_in[0];
    const int*   adj = (const int*)  d_in[1];
    const float* W   = (const float*)d_in[2];
    const float* bW  = (const float*)d_in[3];
    const float* a1  = (const float*)d_in[4];
    const float* a2  = (const float*)d_in[5];
    const float* ba  = (const float*)d_in[6];
    float* out = (float*)d_out;

    static bool attr_set = false;
    if (!attr_set) {
        cudaFuncSetAttribute(k2_fused, cudaFuncAttributeMaxDynamicSharedMemorySize, SMEM_K2);
        cudaFuncSetAttribute(k1_mma, cudaFuncAttributeMaxDynamicSharedMemorySize, SMEM_K1);
        attr_set = true;
    }

    k0_splitW<<<16, 256>>>(W);
    k1_mma<<<NROWS / 32, 256, SMEM_K1>>>(x, bW, a1, a2, ba);
    k2_fused<<<NCTA, 256, SMEM_K2>>>(adj, out);
}

// round 16
// speedup vs baseline: 1.0598x; 1.0598x over previous
#include <cuda_runtime.h>
#include <cuda_fp16.h>
#include <cstdint>

#define NROWS 8192
#define DIN   256
#define DOUT  128
#define KC    64
#define TILE_M 128
#define NCTA  296
#define SLOTS 6

// ---- device-global scratch (no allocations allowed; zero-initialized) ----
__device__ __half g_h[(size_t)NROWS * DOUT];   // h fp16 row-major
__device__ __half g_Wh[(size_t)DIN * DOUT];
__device__ __half g_Wl[(size_t)DIN * DOUT];
__device__ float  g_B[NROWS];
__device__ float  g_D[NROWS];
__device__ float  g_E[NROWS];
__device__ float  g_acc[SLOTS][(size_t)NROWS * DOUT];  // slot partials (zero-init)
__device__ float  g_rs[SLOTS][NROWS];                  // rowsum partials (zero-init)

__device__ __forceinline__ uint32_t smem_u32(const void* p) {
    uint32_t a;
    asm("{ .reg .u64 t; cvta.to.shared.u64 t, %1; cvt.u32.u64 %0, t; }" : "=r"(a) : "l"(p));
    return a;
}

// streaming (evict-first) 16B global loads — for one-pass data
__device__ __forceinline__ int4 ldg_cs(const int4* p) {
    int4 v;
    asm("ld.global.cs.v4.u32 {%0,%1,%2,%3}, [%4];"
        : "=r"(v.x), "=r"(v.y), "=r"(v.z), "=r"(v.w) : "l"(p));
    return v;
}
__device__ __forceinline__ float4 ldg_cs_f4(const float4* p) {
    float4 v;
    asm("ld.global.cs.v4.f32 {%0,%1,%2,%3}, [%4];"
        : "=f"(v.x), "=f"(v.y), "=f"(v.z), "=f"(v.w) : "l"(p));
    return v;
}

#define CP_ASYNC16(dst, src) \
    asm volatile("cp.async.cg.shared.global [%0], [%1], 16;" :: "r"(dst), "l"(src) : "memory")
#define CP_COMMIT() asm volatile("cp.async.commit_group;" ::: "memory")
#define CP_WAIT0()  asm volatile("cp.async.wait_group 0;" ::: "memory")

// ============ K0: split W into fp16 hi/lo (wide grid for latency hiding) ============
// 64 CTAs x 128 threads, 1 float4 per thread (8192 threads cover 32768 elements).
__global__ __launch_bounds__(128) void k0_splitW(const float* __restrict__ W)
{
    size_t e = ((size_t)blockIdx.x * 128 + threadIdx.x) * 4;
    float4 v = __ldg((const float4*)(W + e));
    __half hi[4], lo[4];
    const float* f = (const float*)&v;
    #pragma unroll
    for (int i = 0; i < 4; i++) {
        hi[i] = __float2half_rn(f[i]);
        lo[i] = __float2half_rn(f[i] - __half2float(hi[i]));
    }
    *(uint2*)(g_Wh + e) = *(const uint2*)hi;
    *(uint2*)(g_Wl + e) = *(const uint2*)lo;
}

// ============ K1: h = xW + b via split-fp16 HMMA (x split fused), plus B/D/E ============
#define K1ASTR 72u
#define K1BSTR 136u
#define K1XSTR 68u
#define K1_XS  0u
#define K1_AH  8704u
#define K1_AL  13312u
#define K1_BH  17920u
#define K1_BL  35328u
#define K1BUF  52736u
#define SMEM_K1 (2 * 52736)

__global__ __launch_bounds__(256, 2) void k1_mma(
    const float* __restrict__ x,
    const float* __restrict__ bW, const float* __restrict__ a1,
    const float* __restrict__ a2, const float* __restrict__ ba_p)
{
    extern __shared__ char smem[];
    const uint32_t sb = smem_u32(smem);
    __shared__ float red1[32][4];
    __shared__ float red2[32][4];

    const int tid  = threadIdx.x;
    const int wid  = tid >> 5;
    const int lane = tid & 31;
    const int rb   = blockIdx.x * 32;
    const int mwarp = wid & 1;
    const int nwarp = wid >> 1;

    const int g  = lane >> 3;
    const int l7 = lane & 7;
    const uint32_t aOff = (uint32_t)(mwarp * 16 + (g & 1) * 8 + l7) * K1ASTR + (uint32_t)((g >> 1) * 8);
    const uint32_t bOff = (uint32_t)((g & 1) * 8 + l7) * K1BSTR + (uint32_t)((g >> 1) * 8) + (uint32_t)nwarp * 32u;

    const int crow = tid >> 3;
    const int cc8  = (tid & 7) * 8;

    float facc[4][4];
    #pragma unroll
    for (int n = 0; n < 4; n++)
        #pragma unroll
        for (int c = 0; c < 4; c++) facc[n][c] = 0.f;

    auto stage = [&](int buf, int chunk) {
        const uint32_t base = sb + (uint32_t)buf * K1BUF;
        const int kc = chunk * 64;
        #pragma unroll
        for (int i = 0; i < 2; i++) {
            int pe = tid + 256 * i;
            int r = pe >> 4, p = pe & 15;
            CP_ASYNC16(base + K1_XS + (uint32_t)r * (K1XSTR * 4u) + (uint32_t)p * 16u,
                       x + (size_t)(rb + r) * DIN + kc + p * 4);
        }
        #pragma unroll
        for (int i = 0; i < 4; i++) {
            int e2 = tid + 256 * i;
            int k = e2 >> 4, p = e2 & 15;
            uint32_t d = (uint32_t)k * (K1BSTR * 2u) + (uint32_t)p * 16u;
            CP_ASYNC16(base + K1_BH + d, g_Wh + (size_t)(kc + k) * DOUT + p * 8);
            CP_ASYNC16(base + K1_BL + d, g_Wl + (size_t)(kc + k) * DOUT + p * 8);
        }
        CP_COMMIT();
    };

    stage(0, 0);
    for (int cc = 0; cc < 4; ++cc) {
        const int buf = cc & 1;
        const uint32_t base = sb + (uint32_t)buf * K1BUF;
        CP_WAIT0();
        __syncthreads();

        {
            float v[8];
            uint32_t xaddr = base + K1_XS + (uint32_t)crow * (K1XSTR * 4u) + (uint32_t)cc8 * 4u;
            asm("ld.shared.v4.f32 {%0,%1,%2,%3}, [%4];"
                : "=f"(v[0]), "=f"(v[1]), "=f"(v[2]), "=f"(v[3]) : "r"(xaddr));
            asm("ld.shared.v4.f32 {%0,%1,%2,%3}, [%4];"
                : "=f"(v[4]), "=f"(v[5]), "=f"(v[6]), "=f"(v[7]) : "r"(xaddr + 16u));
            __half hi[8], lo[8];
            #pragma unroll
            for (int i = 0; i < 8; i++) {
                hi[i] = __float2half_rn(v[i]);
                lo[i] = __float2half_rn(v[i] - __half2float(hi[i]));
            }
            uint32_t hdst = base + K1_AH + ((uint32_t)crow * K1ASTR + (uint32_t)cc8) * 2u;
            uint32_t ldst = base + K1_AL + ((uint32_t)crow * K1ASTR + (uint32_t)cc8) * 2u;
            const uint32_t* hw = (const uint32_t*)hi;
            const uint32_t* lw = (const uint32_t*)lo;
            asm volatile("st.shared.v4.b32 [%0], {%1,%2,%3,%4};"
                :: "r"(hdst), "r"(hw[0]), "r"(hw[1]), "r"(hw[2]), "r"(hw[3]) : "memory");
            asm volatile("st.shared.v4.b32 [%0], {%1,%2,%3,%4};"
                :: "r"(ldst), "r"(lw[0]), "r"(lw[1]), "r"(lw[2]), "r"(lw[3]) : "memory");
        }
        __syncthreads();

        if (cc < 3) stage(buf ^ 1, cc + 1);

        #pragma unroll
        for (int ss = 0; ss < 4; ++ss) {
            uint32_t Ah[4], Al[4];
            asm volatile("ldmatrix.sync.aligned.m8n8.x4.shared.b16 {%0,%1,%2,%3}, [%4];"
                : "=r"(Ah[0]), "=r"(Ah[1]), "=r"(Ah[2]), "=r"(Ah[3])
                : "r"(base + K1_AH + (aOff + (uint32_t)ss * 16u) * 2u));
            asm volatile("ldmatrix.sync.aligned.m8n8.x4.shared.b16 {%0,%1,%2,%3}, [%4];"
                : "=r"(Al[0]), "=r"(Al[1]), "=r"(Al[2]), "=r"(Al[3])
                : "r"(base + K1_AL + (aOff + (uint32_t)ss * 16u) * 2u));
            #pragma unroll
            for (int ntg = 0; ntg < 2; ++ntg) {
                uint32_t bh0, bh1, bh2, bh3, bl0, bl1, bl2, bl3;
                uint32_t baddr = (bOff + (uint32_t)ss * 16u * K1BSTR + (uint32_t)ntg * 16u) * 2u;
                asm volatile("ldmatrix.sync.aligned.m8n8.x4.trans.shared.b16 {%0,%1,%2,%3}, [%4];"
                    : "=r"(bh0), "=r"(bh1), "=r"(bh2), "=r"(bh3) : "r"(base + K1_BH + baddr));
                asm volatile("ldmatrix.sync.aligned.m8n8.x4.trans.shared.b16 {%0,%1,%2,%3}, [%4];"
                    : "=r"(bl0), "=r"(bl1), "=r"(bl2), "=r"(bl3) : "r"(base + K1_BL + baddr));
                float* d0 = facc[ntg * 2];
                float* d1 = facc[ntg * 2 + 1];
                asm volatile("mma.sync.aligned.m16n8k16.row.col.f32.f16.f16.f32 "
                    "{%0,%1,%2,%3}, {%4,%5,%6,%7}, {%8,%9}, {%0,%1,%2,%3};"
                    : "+f"(d0[0]), "+f"(d0[1]), "+f"(d0[2]), "+f"(d0[3])
                    : "r"(Ah[0]), "r"(Ah[1]), "r"(Ah[2]), "r"(Ah[3]), "r"(bh0), "r"(bh1));
                asm volatile("mma.sync.aligned.m16n8k16.row.col.f32.f16.f16.f32 "
                    "{%0,%1,%2,%3}, {%4,%5,%6,%7}, {%8,%9}, {%0,%1,%2,%3};"
                    : "+f"(d1[0]), "+f"(d1[1]), "+f"(d1[2]), "+f"(d1[3])
                    : "r"(Ah[0]), "r"(Ah[1]), "r"(Ah[2]), "r"(Ah[3]), "r"(bh2), "r"(bh3));
                asm volatile("mma.sync.aligned.m16n8k16.row.col.f32.f16.f16.f32 "
                    "{%0,%1,%2,%3}, {%4,%5,%6,%7}, {%8,%9}, {%0,%1,%2,%3};"
                    : "+f"(d0[0]), "+f"(d0[1]), "+f"(d0[2]), "+f"(d0[3])
                    : "r"(Ah[0]), "r"(Ah[1]), "r"(Ah[2]), "r"(Ah[3]), "r"(bl0), "r"(bl1));
                asm volatile("mma.sync.aligned.m16n8k16.row.col.f32.f16.f16.f32 "
                    "{%0,%1,%2,%3}, {%4,%5,%6,%7}, {%8,%9}, {%0,%1,%2,%3};"
                    : "+f"(d1[0]), "+f"(d1[1]), "+f"(d1[2]), "+f"(d1[3])
                    : "r"(Ah[0]), "r"(Ah[1]), "r"(Ah[2]), "r"(Ah[3]), "r"(bl2), "r"(bl3));
                asm volatile("mma.sync.aligned.m16n8k16.row.col.f32.f16.f16.f32 "
                    "{%0,%1,%2,%3}, {%4,%5,%6,%7}, {%8,%9}, {%0,%1,%2,%3};"
                    : "+f"(d0[0]), "+f"(d0[1]), "+f"(d0[2]), "+f"(d0[3])
                    : "r"(Al[0]), "r"(Al[1]), "r"(Al[2]), "r"(Al[3]), "r"(bh0), "r"(bh1));
                asm volatile("mma.sync.aligned.m16n8k16.row.col.f32.f16.f16.f32 "
                    "{%0,%1,%2,%3}, {%4,%5,%6,%7}, {%8,%9}, {%0,%1,%2,%3};"
                    : "+f"(d1[0]), "+f"(d1[1]), "+f"(d1[2]), "+f"(d1[3])
                    : "r"(Al[0]), "r"(Al[1]), "r"(Al[2]), "r"(Al[3]), "r"(bh2), "r"(bh3));
            }
        }
        __syncthreads();
    }

    // ---- epilogue: bias, h write, s1/s2, E/B/D ----
    const int r  = lane >> 2;
    const int c2 = (lane & 3) * 2;
    const int row0 = mwarp * 16 + r;
    float s1a = 0.f, s2a = 0.f, s1b = 0.f, s2b = 0.f;

    #pragma unroll
    for (int nt = 0; nt < 4; ++nt) {
        const int col = nwarp * 32 + nt * 8 + c2;
        float2 bv = *(const float2*)&bW[col];
        float2 a1v = *(const float2*)&a1[col];
        float2 a2v = *(const float2*)&a2[col];
        float h00 = facc[nt][0] + bv.x, h01 = facc[nt][1] + bv.y;
        float h10 = facc[nt][2] + bv.x, h11 = facc[nt][3] + bv.y;
        __half2 p0 = __floats2half2_rn(h00, h01);
        __half2 p1 = __floats2half2_rn(h10, h11);
        *(uint32_t*)(g_h + (size_t)(rb + row0) * DOUT + col)     = *(const uint32_t*)&p0;
        *(uint32_t*)(g_h + (size_t)(rb + row0 + 8) * DOUT + col) = *(const uint32_t*)&p1;
        s1a += h00 * a1v.x + h01 * a1v.y;
        s2a += h00 * a2v.x + h01 * a2v.y;
        s1b += h10 * a1v.x + h11 * a1v.y;
        s2b += h10 * a2v.x + h11 * a2v.y;
    }
    #pragma unroll
    for (int m = 1; m <= 2; m <<= 1) {
        s1a += __shfl_xor_sync(0xffffffffu, s1a, m);
        s2a += __shfl_xor_sync(0xffffffffu, s2a, m);
        s1b += __shfl_xor_sync(0xffffffffu, s1b, m);
        s2b += __shfl_xor_sync(0xffffffffu, s2b, m);
    }
    if ((lane & 3) == 0) {
        red1[row0][nwarp] = s1a;  red2[row0][nwarp] = s2a;
        red1[row0 + 8][nwarp] = s1b;  red2[row0 + 8][nwarp] = s2b;
    }
    __syncthreads();
    if (tid < 32) {
        float s1 = red1[tid][0] + red1[tid][1] + red1[tid][2] + red1[tid][3];
        float s2 = red2[tid][0] + red2[tid][1] + red2[tid][2] + red2[tid][3];
        float u = s1 + ba_p[0];
        g_E[rb + tid] = expf(-0.99f * u);
        g_B[rb + tid] = expf(s2);
        g_D[rb + tid] = expf(0.01f * s2);
    }
}

// ============ K2: fused masked-softmax-numerator GEMM (R13) ============
#define PSTR 72u
#define HSTR 136u
#define PBUF (128u * PSTR * 2u)
#define HBUF (64u * HSTR * 2u)
#define SMEM_K2 (2 * 18432 + 2 * 17408)

__global__ __launch_bounds__(256, 2) void k2_fused(const int* __restrict__ adj)
{
    extern __shared__ char smem[];
    const uint32_t sPb = smem_u32(smem);
    const uint32_t sHb = sPb + 2u * PBUF;

    const int tid  = threadIdx.x;
    const int wid  = tid >> 5;
    const int lane = tid & 31;
    const int cta  = blockIdx.x;
    const int slot = cta % SLOTS;

    const int s = (1024 * cta) / 37;
    const int e = (1024 * (cta + 1)) / 37;

    const int tr  = tid >> 3;
    const int jq8 = tid & 7;
    const int hjr = tid >> 2;
    const int hcb = (tid & 3) * 64;

    const int mwarp = wid & 3;
    const int nwarp = wid >> 2;
    const uint32_t ncol0 = (uint32_t)nwarp * 64u;

    const int g  = lane >> 3;
    const int l7 = lane & 7;
    const uint32_t aRow0 = (uint32_t)(mwarp * 32 + (g & 1) * 8 + l7) * PSTR + (uint32_t)((g >> 1) * 8);
    const uint32_t aRow1 = aRow0 + 16u * PSTR;
    const uint32_t bBase = (uint32_t)((g & 1) * 8 + l7) * HSTR + (uint32_t)((g >> 1) * 8) + ncol0;

    const uint32_t sPst = ((uint32_t)tr * PSTR + (uint32_t)jq8 * 8u) * 2u;
    const uint32_t sHst = (uint32_t)hjr * HSTR * 2u + (uint32_t)hcb;

    const float* Bp = g_B + jq8 * 8;
    const float* Dp = g_D + jq8 * 8;

    const int t0 = s >> 7, t1 = (e - 1) >> 7;
    for (int t = t0; t <= t1; ++t) {
        const int c0 = (s > (t << 7)) ? s : (t << 7);
        const int c1 = (e < ((t + 1) << 7)) ? e : ((t + 1) << 7);
        const int rowb = t * TILE_M;

        float Ei[4];
        #pragma unroll
        for (int k = 0; k < 4; k++) Ei[k] = g_E[rowb + tr + 32 * k];

        const int* adjbase = adj + (size_t)(rowb + tr) * NROWS + jq8 * 8;

        float facc[16][4];
        #pragma unroll
        for (int n = 0; n < 16; n++)
            #pragma unroll
            for (int c = 0; c < 4; c++) facc[n][c] = 0.f;
        float rsum[4] = {0.f, 0.f, 0.f, 0.f};

        int4 adjr[8];
        float4 B0r, B1r, D0r, D1r;

        auto produce_k = [&](int k, uint32_t stb) {
            int4 a0 = adjr[2 * k], a1 = adjr[2 * k + 1];
            float v0 = fmaxf(B0r.x, Ei[k] * D0r.x); v0 = a0.x ? v0 : 0.f;
            float v1 = fmaxf(B0r.y, Ei[k] * D0r.y); v1 = a0.y ? v1 : 0.f;
            float v2 = fmaxf(B0r.z, Ei[k] * D0r.z); v2 = a0.z ? v2 : 0.f;
            float v3 = fmaxf(B0r.w, Ei[k] * D0r.w); v3 = a0.w ? v3 : 0.f;
            float v4 = fmaxf(B1r.x, Ei[k] * D1r.x); v4 = a1.x ? v4 : 0.f;
            float v5 = fmaxf(B1r.y, Ei[k] * D1r.y); v5 = a1.y ? v5 : 0.f;
            float v6 = fmaxf(B1r.z, Ei[k] * D1r.z); v6 = a1.z ? v6 : 0.f;
            float v7 = fmaxf(B1r.w, Ei[k] * D1r.w); v7 = a1.w ? v7 : 0.f;
            rsum[k] += ((v0 + v1) + (v2 + v3)) + ((v4 + v5) + (v6 + v7));
            __half2 p0 = __floats2half2_rn(v0, v1);
            __half2 p1 = __floats2half2_rn(v2, v3);
            __half2 p2 = __floats2half2_rn(v4, v5);
            __half2 p3 = __floats2half2_rn(v6, v7);
            asm volatile("st.shared.v4.b32 [%0], {%1,%2,%3,%4};"
                :: "r"(stb + (uint32_t)(32 * k) * PSTR * 2u),
                   "r"(*(const uint32_t*)&p0), "r"(*(const uint32_t*)&p1),
                   "r"(*(const uint32_t*)&p2), "r"(*(const uint32_t*)&p3) : "memory");
        };

        {
            const int jb = (c0 & 127) * KC;
            #pragma unroll
            for (int k = 0; k < 4; k++) {
                const int4* p = (const int4*)(adjbase + (size_t)(32 * k) * NROWS + jb);
                adjr[2 * k]     = ldg_cs(p);
                adjr[2 * k + 1] = ldg_cs(p + 1);
            }
            const char* hsrc = (const char*)g_h + ((size_t)(jb + hjr) * DOUT) * 2 + hcb;
            #pragma unroll
            for (int q = 0; q < 4; q++)
                CP_ASYNC16(sHb + sHst + (uint32_t)q * 16u, hsrc + q * 16);
            CP_COMMIT();
            B0r = __ldg((const float4*)(Bp + jb));
            B1r = __ldg((const float4*)(Bp + jb + 4));
            D0r = __ldg((const float4*)(Dp + jb));
            D1r = __ldg((const float4*)(Dp + jb + 4));
            CP_WAIT0();
            #pragma unroll
            for (int k = 0; k < 4; k++) produce_k(k, sPb + sPst);
        }
        __syncthreads();

        for (int cc = c0; cc < c1; ++cc) {
            const int b = (cc - c0) & 1;
            const uint32_t Pcur = sPb + (uint32_t)b * PBUF;
            const uint32_t Hcur = sHb + (uint32_t)b * HBUF;
            const uint32_t Pnxt = sPb + (uint32_t)(b ^ 1) * PBUF;
            const uint32_t Hnxt = sHb + (uint32_t)(b ^ 1) * HBUF;
            const bool more = (cc + 1 < c1);
            const int jbn = ((cc + 1) & 127) * KC;

            if (more) {
                #pragma unroll
                for (int k = 0; k < 4; k++) {
                    const int4* p = (const int4*)(adjbase + (size_t)(32 * k) * NROWS + jbn);
                    adjr[2 * k]     = ldg_cs(p);
                    adjr[2 * k + 1] = ldg_cs(p + 1);
                }
                const char* hsrc = (const char*)g_h + ((size_t)(jbn + hjr) * DOUT) * 2 + hcb;
                #pragma unroll
                for (int q = 0; q < 4; q++)
                    CP_ASYNC16(Hnxt + sHst + (uint32_t)q * 16u, hsrc + q * 16);
                CP_COMMIT();
                B0r = __ldg((const float4*)(Bp + jbn));
                B1r = __ldg((const float4*)(Bp + jbn + 4));
                D0r = __ldg((const float4*)(Dp + jbn));
                D1r = __ldg((const float4*)(Dp + jbn + 4));
            }

            #pragma unroll
            for (int ss = 0; ss < 4; ++ss) {
                uint32_t A0[4], A1[4];
                asm volatile("ldmatrix.sync.aligned.m8n8.x4.shared.b16 {%0,%1,%2,%3}, [%4];"
                    : "=r"(A0[0]), "=r"(A0[1]), "=r"(A0[2]), "=r"(A0[3])
                    : "r"(Pcur + (aRow0 + (uint32_t)ss * 16u) * 2u));
                asm volatile("ldmatrix.sync.aligned.m8n8.x4.shared.b16 {%0,%1,%2,%3}, [%4];"
                    : "=r"(A1[0]), "=r"(A1[1]), "=r"(A1[2]), "=r"(A1[3])
                    : "r"(Pcur + (aRow1 + (uint32_t)ss * 16u) * 2u));
                #pragma unroll
                for (int nt = 0; nt < 4; ++nt) {
                    uint32_t b0, b1, b2, b3;
                    asm volatile("ldmatrix.sync.aligned.m8n8.x4.trans.shared.b16 {%0,%1,%2,%3}, [%4];"
                        : "=r"(b0), "=r"(b1), "=r"(b2), "=r"(b3)
                        : "r"(Hcur + (bBase + (uint32_t)ss * 16u * HSTR + (uint32_t)nt * 16u) * 2u));
                    float* d00 = facc[nt * 2];
                    float* d01 = facc[nt * 2 + 1];
                    float* d10 = facc[8 + nt * 2];
                    float* d11 = facc[8 + nt * 2 + 1];
                    asm volatile("mma.sync.aligned.m16n8k16.row.col.f32.f16.f16.f32 "
                        "{%0,%1,%2,%3}, {%4,%5,%6,%7}, {%8,%9}, {%0,%1,%2,%3};"
                        : "+f"(d00[0]), "+f"(d00[1]), "+f"(d00[2]), "+f"(d00[3])
                        : "r"(A0[0]), "r"(A0[1]), "r"(A0[2]), "r"(A0[3]), "r"(b0), "r"(b1));
                    asm volatile("mma.sync.aligned.m16n8k16.row.col.f32.f16.f16.f32 "
                        "{%0,%1,%2,%3}, {%4,%5,%6,%7}, {%8,%9}, {%0,%1,%2,%3};"
                        : "+f"(d01[0]), "+f"(d01[1]), "+f"(d01[2]), "+f"(d01[3])
                        : "r"(A0[0]), "r"(A0[1]), "r"(A0[2]), "r"(A0[3]), "r"(b2), "r"(b3));
                    asm volatile("mma.sync.aligned.m16n8k16.row.col.f32.f16.f16.f32 "
                        "{%0,%1,%2,%3}, {%4,%5,%6,%7}, {%8,%9}, {%0,%1,%2,%3};"
                        : "+f"(d10[0]), "+f"(d10[1]), "+f"(d10[2]), "+f"(d10[3])
                        : "r"(A1[0]), "r"(A1[1]), "r"(A1[2]), "r"(A1[3]), "r"(b0), "r"(b1));
                    asm volatile("mma.sync.aligned.m16n8k16.row.col.f32.f16.f16.f32 "
                        "{%0,%1,%2,%3}, {%4,%5,%6,%7}, {%8,%9}, {%0,%1,%2,%3};"
                        : "+f"(d11[0]), "+f"(d11[1]), "+f"(d11[2]), "+f"(d11[3])
                        : "r"(A1[0]), "r"(A1[1]), "r"(A1[2]), "r"(A1[3]), "r"(b2), "r"(b3));
                }
                if (more) produce_k(ss, Pnxt + sPst);
            }

            CP_WAIT0();
            __syncthreads();
        }

        {
            const int r  = lane >> 2;
            const int c2 = (lane & 3) * 2;
            #pragma unroll
            for (int mt = 0; mt < 2; ++mt) {
                const int row0 = rowb + mwarp * 32 + mt * 16 + r;
                float* dst0 = &g_acc[slot][(size_t)row0 * DOUT];
                float* dst1 = dst0 + (size_t)8 * DOUT;
                #pragma unroll
                for (int nt = 0; nt < 4; ++nt) {
                    #pragma unroll
                    for (int hh = 0; hh < 2; ++hh) {
                        const float* f = facc[mt * 8 + nt * 2 + hh];
                        int col = nwarp * 64 + nt * 16 + hh * 8 + c2;
                        *(float2*)(dst0 + col) = make_float2(f[0], f[1]);
                        *(float2*)(dst1 + col) = make_float2(f[2], f[3]);
                    }
                }
            }
        }
        #pragma unroll
        for (int m = 1; m <= 4; m <<= 1) {
            #pragma unroll
            for (int k = 0; k < 4; k++)
                rsum[k] += __shfl_xor_sync(0xffffffffu, rsum[k], m);
        }
        if (jq8 == 0) {
            #pragma unroll
            for (int k = 0; k < 4; k++)
                g_rs[slot][rowb + tr + 32 * k] = rsum[k];
        }
        __syncthreads();
    }
}

// ============ K3: sum slot partials, normalize (R13 version) ============
__global__ __launch_bounds__(256) void k3_final(float* __restrict__ out)
{
    const int idx = blockIdx.x * 256 + threadIdx.x;
    const int row = idx >> 5;
    float rs = 0.f;
    #pragma unroll
    for (int s2 = 0; s2 < SLOTS; s2++) rs += g_rs[s2][row];
    const float inv = 1.0f / rs;
    float ox = 0.f, oy = 0.f, oz = 0.f, ow = 0.f;
    #pragma unroll
    for (int s2 = 0; s2 < SLOTS; s2++) {
        float4 a = ldg_cs_f4(&((const float4*)g_acc[s2])[idx]);
        ox += a.x; oy += a.y; oz += a.z; ow += a.w;
    }
    float4 o;
    o.x = ox * inv; o.y = oy * inv; o.z = oz * inv; o.w = ow * inv;
    ((float4*)out)[idx] = o;
}

extern "C" void kernel_launch(void* const* d_in, const int* in_sizes, int n_in,
                              void* d_out, int out_size) {
    const float* x   = (const float*)d_in[0];
    const int*   adj = (const int*)  d_in[1];
    const float* W   = (const float*)d_in[2];
    const float* bW  = (const float*)d_in[3];
    const float* a1  = (const float*)d_in[4];
    const float* a2  = (const float*)d_in[5];
    const float* ba  = (const float*)d_in[6];
    float* out = (float*)d_out;

    static bool attr_set = false;
    if (!attr_set) {
        cudaFuncSetAttribute(k2_fused, cudaFuncAttributeMaxDynamicSharedMemorySize, SMEM_K2);
        cudaFuncSetAttribute(k1_mma, cudaFuncAttributeMaxDynamicSharedMemorySize, SMEM_K1);
        attr_set = true;
    }

    k0_splitW<<<64, 128>>>(W);
    k1_mma<<<NROWS / 32, 256, SMEM_K1>>>(x, bW, a1, a2, ba);
    k2_fused<<<NCTA, 256, SMEM_K2>>>(adj);
    k3_final<<<(NROWS * DOUT / 4) / 256, 256>>>(out);
}